// round 13
// baseline (speedup 1.0000x reference)
#include <cuda_runtime.h>
#include <cuda_bf16.h>
#include <cstdint>

// RWKV WKV recurrence, single-pass serial-in-T, warp-per-block cp.async ring.
//   a_t = exp(w_t)*a_{t-1} + exp(k_t)
//   b_t = exp(w_t)*b_{t-1} + exp(k_t)*v_t
//   out_t = b_t / a_t
// One 32-thread block per (batch, 32-wide d-group): 512 blocks / 512 warps.
// 16-slot (48KB) smem ring. R12 confirmed the per-warp outstanding-LDGSTS cap
// (M_max~55) as the knee: wait_group(8)=48 outstanding beat both 36 and 84.
// This round: (a) WAITG=9 -> 54 outstanding, exactly at the cap; (b) issue is
// INTERLEAVED into the compute loop (one cp.async after each of the first 6
// steps) so the 4 warps/SM feed the L1tex wavefront queue steadily instead of
// in 24-wavefront bursts. Minimal traffic: 3 reads + 1 write = 537MB.

#define BATCH 16
#define TLEN  2048
#define DIM   1024
#define GROUP 32
#define SPB   8                        // steps per ring slot
#define NB    16                       // ring slots (48KB)
#define WAITG 9                        // outstanding groups: 9*6=54 <= M_max~55
#define NBT   (TLEN / SPB)             // 256 iterations
#define TPT   6                        // cp.async tiles per thread per slot

__device__ __forceinline__ void cp_async16(uint32_t s, const void* g) {
    asm volatile("cp.async.cg.shared.global [%0], [%1], 16;" :: "r"(s), "l"(g));
}

__global__ __launch_bounds__(GROUP, 4)
void wkv_warp_ring_kernel(const float* __restrict__ K,
                          const float* __restrict__ V,
                          const float* __restrict__ W,
                          float* __restrict__ O) {
    // ring[slot][arr][step][d] : slot<16, arr<3, step<8, d<32  -> 49152 B
    __shared__ float ring[NB * 3 * SPB * GROUP];

    const int tid = threadIdx.x;
    const int b   = blockIdx.x >> 5;          // batch
    const int g   = blockIdx.x & 31;          // d-group of 32

    const size_t rowBase = (size_t)b * TLEN * DIM + (size_t)g * GROUP;
    const uint32_t sBase = (uint32_t)__cvta_generic_to_shared(ring);

    const float* arrs[3] = { K, V, W };

    // Issue ONE 16B tile (index j in 0..5) of ring slot for batch bt.
    auto issue_tile = [&](int bt, int j) {
        const int slot = bt & (NB - 1);
        const int step0 = bt * SPB;
        int i   = tid + GROUP * j;            // 0..191
        int arr = i >> 6;                     // /64  (8 tiles * 8 steps per array)
        int rem = i & 63;
        int t   = rem >> 3;                   // step within slot
        int col = rem & 7;                    // 16B column within 128B row
        size_t goff = rowBase + (size_t)(step0 + t) * DIM + (size_t)col * 4;
        uint32_t soff = (uint32_t)((((slot * 3 + arr) * SPB + t) * GROUP + col * 4) * 4);
        cp_async16(sBase + soff, arrs[arr] + goff);
    };

    // ---- prologue: fill NB-1 ring slots (completion gated by WAITG below) ----
#pragma unroll
    for (int bt = 0; bt < NB - 1; bt++) {
#pragma unroll
        for (int j = 0; j < TPT; j++) issue_tile(bt, j);
        asm volatile("cp.async.commit_group;");
    }

    float a = 0.0f, s = 0.0f;
    float* out = O + rowBase + tid;

    for (int bt = 0; bt < NBT; bt++) {
        // Slot bt's group was committed NB-1 iterations back; wait_group(WAITG)
        // leaves >=6 groups of slack beyond it, and caps in-flight LDGSTS at
        // 9*6 = 54 per warp (~M_max). Uniform commit cadence through the tail.
        asm volatile("cp.async.wait_group %0;" :: "n"(WAITG) : "memory");
        __syncwarp();   // this slot's data visible to all lanes

        const int slot = bt & (NB - 1);
        const float* rk = &ring[((slot * 3 + 0) * SPB) * GROUP + tid];
        const float* rv = &ring[((slot * 3 + 1) * SPB) * GROUP + tid];
        const float* rw = &ring[((slot * 3 + 2) * SPB) * GROUP + tid];

        const int ft = bt + NB - 1;           // slot being refilled (== bt-1 mod 16)
        const bool doIssue = (ft < NBT);

#pragma unroll
        for (int u = 0; u < SPB; u++) {
            float lk = rk[u * GROUP];
            float lv = rv[u * GROUP];
            float lw = rw[u * GROUP];
            // Interleave one prefetch tile per step (first 6 steps): steady
            // L1tex feed instead of a 24-wavefront burst at iteration top.
            if (u < TPT && doIssue) issue_tile(ft, u);
            float ek = __expf(lk);
            float ew = __expf(lw);
            a = fmaf(ew, a, ek);
            s = fmaf(ew, s, ek * lv);
            __stcs(&out[(size_t)(bt * SPB + u) * DIM], __fdividef(s, a));
        }
        asm volatile("cp.async.commit_group;");
        __syncwarp();   // all lanes done reading before slot is overwritten
    }
}

extern "C" void kernel_launch(void* const* d_in, const int* in_sizes, int n_in,
                              void* d_out, int out_size) {
    const float* k = (const float*)d_in[0];
    const float* v = (const float*)d_in[1];
    const float* w = (const float*)d_in[2];
    float* out = (float*)d_out;

    wkv_warp_ring_kernel<<<BATCH * (DIM / GROUP), GROUP>>>(k, v, w, out);
}

// round 15
// speedup vs baseline: 1.0356x; 1.0356x over previous
#include <cuda_runtime.h>
#include <cuda_bf16.h>
#include <cstdint>

// RWKV WKV recurrence, single-pass serial-in-T, warp-per-block cp.async ring.
//   a_t = exp(w_t)*a_{t-1} + exp(k_t)
//   b_t = exp(w_t)*b_{t-1} + exp(k_t)*v_t
//   out_t = b_t / a_t
// One 32-thread block per (batch, 32-wide d-group): 512 blocks / 512 warps.
// 16-slot (48KB) smem ring, batched 6-tile cp.async issue at iteration top
// (R12 structure, proven 82.4us; R13's interleaved issue regressed and is
// reverted). Single knob vs R12: wait_group 8 -> 9, raising per-warp in-flight
// LDGSTS from 48 to 54, at the M_max~55 LSU tracking cap.
// Minimal traffic: 3 reads + 1 write = 537MB.
// (Resubmission: R14 bench run died to a container infra failure.)

#define BATCH 16
#define TLEN  2048
#define DIM   1024
#define GROUP 32
#define SPB   8                        // steps per ring slot
#define NB    16                       // ring slots (48KB; reuse slack >> lead)
#define WAITG 9                        // outstanding groups: 9*6=54 ~= M_max
#define NBT   (TLEN / SPB)             // 256 iterations
#define TILES_PER_THREAD 6             // 3 arr * 8 steps * 8 tiles / 32 thr

__device__ __forceinline__ void cp_async16(uint32_t s, const void* g) {
    asm volatile("cp.async.cg.shared.global [%0], [%1], 16;" :: "r"(s), "l"(g));
}

__global__ __launch_bounds__(GROUP, 4)
void wkv_warp_ring_kernel(const float* __restrict__ K,
                          const float* __restrict__ V,
                          const float* __restrict__ W,
                          float* __restrict__ O) {
    // ring[slot][arr][step][d] : slot<16, arr<3, step<8, d<32  -> 49152 B
    __shared__ float ring[NB * 3 * SPB * GROUP];

    const int tid = threadIdx.x;
    const int b   = blockIdx.x >> 5;          // batch
    const int g   = blockIdx.x & 31;          // d-group of 32

    const size_t rowBase = (size_t)b * TLEN * DIM + (size_t)g * GROUP;
    const uint32_t sBase = (uint32_t)__cvta_generic_to_shared(ring);

    const float* arrs[3] = { K, V, W };

    // Issue all cp.asyncs for one ring slot (8 steps x 3 arrays x 128B rows).
    auto issue_batch = [&](int bt) {
        const int slot = bt & (NB - 1);
        const int step0 = bt * SPB;
#pragma unroll
        for (int j = 0; j < TILES_PER_THREAD; j++) {
            int i   = tid + GROUP * j;        // 0..191
            int arr = i >> 6;                 // /64  (8 tiles * 8 steps per array)
            int rem = i & 63;
            int t   = rem >> 3;               // step within slot
            int col = rem & 7;                // 16B column within 128B row
            size_t goff = rowBase + (size_t)(step0 + t) * DIM + (size_t)col * 4;
            uint32_t soff = (uint32_t)((((slot * 3 + arr) * SPB + t) * GROUP + col * 4) * 4);
            cp_async16(sBase + soff, arrs[arr] + goff);
        }
    };

    // ---- prologue: fill NB-1 ring slots (completion gated by WAITG below) ----
#pragma unroll
    for (int bt = 0; bt < NB - 1; bt++) {
        issue_batch(bt);
        asm volatile("cp.async.commit_group;");
    }

    float a = 0.0f, s = 0.0f;
    float* out = O + rowBase + tid;

    for (int bt = 0; bt < NBT; bt++) {
        // Keep pipeline full; commit every iteration (possibly empty group)
        // so wait_group arithmetic stays uniform through the tail.
        if (bt + NB - 1 < NBT) issue_batch(bt + NB - 1);
        asm volatile("cp.async.commit_group;");
        // <=WAITG newest groups outstanding: slot bt complete (>=6 groups of
        // slack with NB=16), 54 LDGSTS in flight ~ M_max per warp.
        asm volatile("cp.async.wait_group %0;" :: "n"(WAITG) : "memory");
        __syncwarp();   // this slot's data visible to all lanes

        const int slot = bt & (NB - 1);
        const float* rk = &ring[((slot * 3 + 0) * SPB) * GROUP + tid];
        const float* rv = &ring[((slot * 3 + 1) * SPB) * GROUP + tid];
        const float* rw = &ring[((slot * 3 + 2) * SPB) * GROUP + tid];

#pragma unroll
        for (int u = 0; u < SPB; u++) {
            float lk = rk[u * GROUP];
            float lv = rv[u * GROUP];
            float lw = rw[u * GROUP];
            float ek = __expf(lk);
            float ew = __expf(lw);
            a = fmaf(ew, a, ek);
            s = fmaf(ew, s, ek * lv);
            __stcs(&out[(size_t)(bt * SPB + u) * DIM], __fdividef(s, a));
        }
        __syncwarp();   // all lanes done reading before slot is overwritten
    }
}

extern "C" void kernel_launch(void* const* d_in, const int* in_sizes, int n_in,
                              void* d_out, int out_size) {
    const float* k = (const float*)d_in[0];
    const float* v = (const float*)d_in[1];
    const float* w = (const float*)d_in[2];
    float* out = (float*)d_out;

    wkv_warp_ring_kernel<<<BATCH * (DIM / GROUP), GROUP>>>(k, v, w, out);
}